// round 17
// baseline (speedup 1.0000x reference)
#include <cuda_runtime.h>
#include <cuda_bf16.h>
#include <cuda_fp16.h>
#include <cstdint>

#define NB 8
#define NS 1024
#define ND 1024
#define NH 16
#define NDH 64

// ---------------- scratch (static device globals) ----------------
__device__ __align__(128) __half g_A[(size_t)NB * NS * 1024];          // xh
__device__ __align__(128) __half g_Bm[3 * (size_t)ND * 1024];          // wh
// attention operands, plain fp16: [bh][s][64]
__device__ __align__(128) __half g_Qs[(size_t)NB * NH * NS * NDH];     // qh*0.125*log2e
__device__ __align__(128) __half g_Ks[(size_t)NB * NH * NS * NDH];     // kh
__device__ __align__(128) __half g_Vs[(size_t)NB * NH * NS * NDH];     // vh

// ---------------- PTX helpers (compute_103-safe) ----------------
__device__ __forceinline__ uint32_t smem_u32(const void* p) {
    uint32_t a;
    asm("{ .reg .u64 t; cvta.to.shared.u64 t, %1; cvt.u32.u64 %0, t; }" : "=r"(a) : "l"(p));
    return a;
}
__device__ __forceinline__ void cp_async16(uint32_t dst, const void* src) {
    asm volatile("cp.async.cg.shared.global [%0], [%1], 16;" :: "r"(dst), "l"(src));
}
#define CP_COMMIT() asm volatile("cp.async.commit_group;" ::: "memory")
#define CP_WAIT(n)  asm volatile("cp.async.wait_group %0;" :: "n"(n) : "memory")

__device__ __forceinline__ void ldsm4(uint32_t* r, uint32_t addr) {
    asm volatile("ldmatrix.sync.aligned.m8n8.x4.shared.b16 {%0,%1,%2,%3}, [%4];"
                 : "=r"(r[0]), "=r"(r[1]), "=r"(r[2]), "=r"(r[3]) : "r"(addr));
}
__device__ __forceinline__ void ldsm4t(uint32_t* r, uint32_t addr) {
    asm volatile("ldmatrix.sync.aligned.m8n8.x4.trans.shared.b16 {%0,%1,%2,%3}, [%4];"
                 : "=r"(r[0]), "=r"(r[1]), "=r"(r[2]), "=r"(r[3]) : "r"(addr));
}
// fp16 mma
__device__ __forceinline__ void mma16816h(float* c, const uint32_t* a, const uint32_t* b) {
    asm volatile("mma.sync.aligned.m16n8k16.row.col.f32.f16.f16.f32 "
                 "{%0,%1,%2,%3}, {%4,%5,%6,%7}, {%8,%9}, {%0,%1,%2,%3};"
                 : "+f"(c[0]), "+f"(c[1]), "+f"(c[2]), "+f"(c[3])
                 : "r"(a[0]), "r"(a[1]), "r"(a[2]), "r"(a[3]), "r"(b[0]), "r"(b[1]));
}
__device__ __forceinline__ void mma16816hv(float* c, const uint32_t* a, uint32_t b0, uint32_t b1) {
    asm volatile("mma.sync.aligned.m16n8k16.row.col.f32.f16.f16.f32 "
                 "{%0,%1,%2,%3}, {%4,%5,%6,%7}, {%8,%9}, {%0,%1,%2,%3};"
                 : "+f"(c[0]), "+f"(c[1]), "+f"(c[2]), "+f"(c[3])
                 : "r"(a[0]), "r"(a[1]), "r"(a[2]), "r"(a[3]), "r"(b0), "r"(b1));
}
__device__ __forceinline__ float ex2f(float x) {
    float r;
    asm("ex2.approx.ftz.f32 %0, %1;" : "=f"(r) : "f"(x));
    return r;
}
__device__ __forceinline__ void stcs4(float* p, float4 v) {
    asm volatile("st.global.cs.v4.f32 [%0], {%1,%2,%3,%4};"
                 :: "l"(p), "f"(v.x), "f"(v.y), "f"(v.z), "f"(v.w) : "memory");
}
__device__ __forceinline__ uint32_t sw128(uint32_t off) { return off ^ ((off >> 3) & 0x70); }

// ============================================================================
// Fused prep: one launch converts x, Wq, Wk, Wv to fp16.
// blocks [0, 8192)            -> x  (8.4M elems)
// blocks [8192, 8192+3072)    -> W  (z = (blk-8192)/1024)
// ============================================================================
__global__ __launch_bounds__(256) void prep_kernel(
    const float* __restrict__ x,
    const float* __restrict__ Wq, const float* __restrict__ Wk, const float* __restrict__ Wv)
{
    int blk = blockIdx.x;
    const float* src;
    __half* dst;
    size_t e;
    if (blk < 8192) {
        src = x; dst = g_A;
        e = ((size_t)blk * 256 + threadIdx.x) * 4;
    } else {
        int wb = blk - 8192;
        int z = wb >> 10;
        src = (z == 0) ? Wq : (z == 1) ? Wk : Wv;
        dst = g_Bm + (size_t)z * ND * 1024;
        e = ((size_t)(wb & 1023) * 256 + threadIdx.x) * 4;
    }
    float4 v = *(const float4*)&src[e];
    __half2 h01 = __floats2half2_rn(v.x, v.y);
    __half2 h23 = __floats2half2_rn(v.z, v.w);
    *(__half2*)&dst[e]     = h01;
    *(__half2*)&dst[e + 2] = h23;
}

// ============================================================================
// QKV GEMM via mma.sync fp16, K=1024 (16 k-tiles of 64). CTA 128x128,
// 3-stage cp.async pipeline, 2 CTAs/SM.
// Q scale folds 1/8 AND log2(e) so attention uses exp2 directly.
// ============================================================================
#define STAGE_BYTES 32768
#define QKV_SMEM (3 * STAGE_BYTES)

__global__ __launch_bounds__(256, 2)
void qkv_mma_kernel(const float* __restrict__ bq, const float* __restrict__ bk,
                    const float* __restrict__ bv)
{
    extern __shared__ char smraw[];
    __shared__ float biasS[128];
    uint32_t sm = smem_u32(smraw);

    int t = threadIdx.x;
    int wid = t >> 5, lane = t & 31;
    int warp_m = wid & 1, warp_n = wid >> 1;

    int bx = blockIdx.x;
    int z = bx >> 3;
    int n0 = (bx & 7) * 128;
    int m0 = blockIdx.y * 128;

    const float* bias = (z == 0) ? bq : (z == 1) ? bk : bv;
    const __half* Asrc = g_A + (size_t)m0 * 1024;
    const __half* Bsrc = g_Bm + (size_t)z * ND * 1024 + (size_t)n0 * 1024;

    if (t < 128) biasS[t] = bias[n0 + t];

    auto load_tile = [&](int kt, int s) {
        uint32_t base = sm + s * STAGE_BYTES;
        int k0 = kt * 64;
        #pragma unroll
        for (int i = 0; i < 8; i++) {
            int c = t + i * 256;
            int row = c >> 3, col = c & 7;
            uint32_t off = sw128((uint32_t)((row & 127) * 128 + col * 16));
            const __half* src = (row < 128)
                ? Asrc + (size_t)row * 1024 + k0 + col * 8
                : Bsrc + (size_t)(row - 128) * 1024 + k0 + col * 8;
            cp_async16(base + (row < 128 ? 0u : 16384u) + off, src);
        }
    };

    float acc[4][4][4];
    #pragma unroll
    for (int mt = 0; mt < 4; mt++)
        #pragma unroll
        for (int nt = 0; nt < 4; nt++)
            #pragma unroll
            for (int r = 0; r < 4; r++) acc[mt][nt][r] = 0.f;

    uint32_t a_row = (uint32_t)(warp_m * 64 + (lane & 15));
    uint32_t a_kb  = (uint32_t)((lane >> 4) << 4);
    uint32_t b_row = (uint32_t)(warp_n * 32 + (lane & 15));

    load_tile(0, 0); CP_COMMIT();
    load_tile(1, 1); CP_COMMIT();

    int cur = 0;
    for (int kt = 0; kt < 16; kt++) {
        if (kt + 1 < 16) CP_WAIT(1); else CP_WAIT(0);
        __syncthreads();
        if (kt + 2 < 16) {
            int nxt = cur + 2; if (nxt >= 3) nxt -= 3;
            load_tile(kt + 2, nxt); CP_COMMIT();
        }

        uint32_t abase = sm + cur * STAGE_BYTES;
        uint32_t bbase = abase + 16384u;
        #pragma unroll
        for (int ks = 0; ks < 4; ks++) {
            uint32_t kb = (uint32_t)(ks * 32);
            uint32_t af[4][4], bw[2][4];
            #pragma unroll
            for (int mt = 0; mt < 4; mt++)
                ldsm4(af[mt], abase + sw128((a_row + mt * 16) * 128 + kb + a_kb));
            #pragma unroll
            for (int p = 0; p < 2; p++)
                ldsm4(bw[p], bbase + sw128((b_row + p * 16) * 128 + kb + a_kb));
            #pragma unroll
            for (int mt = 0; mt < 4; mt++)
                #pragma unroll
                for (int p = 0; p < 2; p++) {
                    mma16816hv(acc[mt][2 * p],     af[mt], bw[p][0], bw[p][2]);
                    mma16816hv(acc[mt][2 * p + 1], af[mt], bw[p][1], bw[p][3]);
                }
        }
        __syncthreads();
        cur = cur + 1; if (cur >= 3) cur = 0;
    }

    // ---- epilogue: bias (+0.125*log2e for Q) -> plain fp16 attn operands ----
    int gq = lane >> 2;
    float scale = (z == 0) ? 0.125f * 1.44269504f : 1.0f;
    __half* dst = (z == 0) ? g_Qs : (z == 1) ? g_Ks : g_Vs;
    #pragma unroll
    for (int mt = 0; mt < 4; mt++) {
        int m_lo = m0 + warp_m * 64 + mt * 16 + gq;
        #pragma unroll
        for (int half = 0; half < 2; half++) {
            int m = m_lo + half * 8;
            int b = m >> 10, s = m & 1023;
            #pragma unroll
            for (int nt = 0; nt < 4; nt++) {
                int nc = warp_n * 32 + nt * 8 + (lane & 3) * 2;
                int n = n0 + nc;
                int h = n >> 6, dh = n & 63;
                int bh = b * NH + h;
                float c0 = (acc[mt][nt][half * 2 + 0] + biasS[nc]) * scale;
                float c1 = (acc[mt][nt][half * 2 + 1] + biasS[nc + 1]) * scale;
                __half2 hv = __floats2half2_rn(c0, c1);
                size_t o = ((size_t)bh * NS + s) * NDH + dh;
                *(__half2*)&dst[o] = hv;
            }
        }
    }
}

// ============================================================================
// Attention via mma.sync fp16, fused normalization. CTA: 32 q x one (b,h),
// 2 CTAs/SM (112KB smem). 8 k-tiles of 128. All 8 P tiles (fp16, 8KB each)
// stay in smem; att written once, normalized, in the tail (streaming stores).
// Q (4KB) aliased over P[7]. K single-buffered; V double-buffered.
// Scores are in log2 domain -> ex2.approx directly.
// ============================================================================
#define P_OFF  0u                       // 8 tiles x 8192 = 65536
#define QAL_OFF (P_OFF + 7u * 8192u)    // Q alias (4KB) over P[7]
#define K_OFF  65536u                   // 16384
#define V_OFF  81920u                   // 2 bufs x 16384 = 32768
#define RS_OFF 114688u                  // 32 floats
#define ATT_SMEM 114816u

__global__ __launch_bounds__(256, 2)
void attn_mma_kernel(float* __restrict__ out_ctx, float* __restrict__ out_att)
{
    extern __shared__ char smraw[];
    uint32_t sm = smem_u32(smraw);
    float* rowsumS = (float*)(smraw + RS_OFF);

    int t = threadIdx.x;
    int wid = t >> 5, lane = t & 31;
    int warp_m = wid & 1, warp_n = wid >> 1;
    int bh = blockIdx.y;
    int q0 = blockIdx.x * 32;

    const __half* Qg = g_Qs + ((size_t)bh * NS + q0) * NDH;
    const __half* Kg = g_Ks + (size_t)bh * NS * NDH;
    const __half* Vg = g_Vs + (size_t)bh * NS * NDH;

    auto load_k = [&](int kt) {
        #pragma unroll
        for (int i = 0; i < 4; i++) {
            int c = t + i * 256;
            int row = (c >> 3) & 127, col = c & 7;
            cp_async16(sm + K_OFF + sw128((uint32_t)(row * 128 + col * 16)),
                       Kg + ((size_t)(kt * 128 + row)) * NDH + col * 8);
        }
    };
    auto load_v = [&](int kt, int buf) {
        #pragma unroll
        for (int i = 0; i < 4; i++) {
            int c = t + i * 256;
            int row = (c >> 3) & 127, col = c & 7;
            cp_async16(sm + V_OFF + buf * 16384u
                          + sw128((uint32_t)(row * 128 + col * 16)),
                       Vg + ((size_t)(kt * 128 + row)) * NDH + col * 8);
        }
    };

    // prologue: Q (into alias region) + K(0) | V(0) | V(1)
    {
        int row = (t >> 3) & 31, col = t & 7;
        cp_async16(sm + QAL_OFF + sw128((uint32_t)(row * 128 + col * 16)),
                   Qg + (size_t)row * NDH + col * 8);
    }
    load_k(0); CP_COMMIT();
    load_v(0, 0); CP_COMMIT();
    load_v(1, 1); CP_COMMIT();
    if (t < 32) rowsumS[t] = 0.f;

    float ctx[2][4];
    #pragma unroll
    for (int nt = 0; nt < 2; nt++)
        #pragma unroll
        for (int r = 0; r < 4; r++) ctx[nt][r] = 0.f;

    uint32_t a_row = (uint32_t)(warp_m * 16 + (lane & 15));
    uint32_t a_kb  = (uint32_t)((lane >> 4) << 4);
    uint32_t b_row = (uint32_t)(warp_n * 32 + (lane & 15));

    uint32_t afq[4][4];    // Q fragments, resident in registers

    for (int kt = 0; kt < 8; kt++) {
        if (kt < 7) { CP_WAIT(1); } else { CP_WAIT(0); }
        __syncthreads();

        if (kt == 0) {
            #pragma unroll
            for (int ks = 0; ks < 4; ks++)
                ldsm4(afq[ks], sm + QAL_OFF
                      + sw128(a_row * 128 + (uint32_t)(ks * 32) + a_kb));
        }

        // ---- QK: M32 x N128 x K64 (warp tile M16 x N32, B via 2x ldsm4) ----
        float sacc[4][4];
        #pragma unroll
        for (int nt = 0; nt < 4; nt++)
            #pragma unroll
            for (int r = 0; r < 4; r++) sacc[nt][r] = 0.f;

        #pragma unroll
        for (int ks = 0; ks < 4; ks++) {
            uint32_t kb = (uint32_t)(ks * 32);
            uint32_t bw[2][4];
            #pragma unroll
            for (int p = 0; p < 2; p++)
                ldsm4(bw[p], sm + K_OFF
                             + sw128((b_row + p * 16) * 128 + kb + a_kb));
            #pragma unroll
            for (int p = 0; p < 2; p++) {
                mma16816hv(sacc[2 * p],     afq[ks], bw[p][0], bw[p][2]);
                mma16816hv(sacc[2 * p + 1], afq[ks], bw[p][1], bw[p][3]);
            }
        }

        // ---- exp2 -> P[kt] (fp16, smem only) + rowsum ----
        uint32_t pbase = (uint32_t)(P_OFF + kt * 8192);
        {
            float p0 = 0.f, p1 = 0.f;
            int r0 = warp_m * 16 + (lane >> 2);
            #pragma unroll
            for (int nt = 0; nt < 4; nt++) {
                int kc = warp_n * 32 + nt * 8 + (lane & 3) * 2;
                float e0 = ex2f(sacc[nt][0]);
                float e1 = ex2f(sacc[nt][1]);
                float e2 = ex2f(sacc[nt][2]);
                float e3 = ex2f(sacc[nt][3]);
                p0 += e0 + e1; p1 += e2 + e3;
                __half2 h0 = __floats2half2_rn(e0, e1);
                __half2 h1 = __floats2half2_rn(e2, e3);
                uint32_t po  = pbase + (uint32_t)((kc >> 6) * 4096)
                             + sw128((uint32_t)(r0 * 128 + (kc & 63) * 2));
                uint32_t po8 = pbase + (uint32_t)((kc >> 6) * 4096)
                             + sw128((uint32_t)((r0 + 8) * 128 + (kc & 63) * 2));
                *(__half2*)(smraw + po)  = h0;
                *(__half2*)(smraw + po8) = h1;
            }
            p0 += __shfl_xor_sync(0xffffffffu, p0, 1);
            p0 += __shfl_xor_sync(0xffffffffu, p0, 2);
            p1 += __shfl_xor_sync(0xffffffffu, p1, 1);
            p1 += __shfl_xor_sync(0xffffffffu, p1, 2);
            if ((lane & 3) == 0) {
                atomicAdd(&rowsumS[r0], p0);
                atomicAdd(&rowsumS[r0 + 8], p1);
            }
        }
        __syncthreads();   // P[kt] ready; all warps done with K(kt)
        if (kt + 1 < 8) { load_k(kt + 1); CP_COMMIT(); }   // hidden behind AV

        // ---- AV: ctx += P * V, M32 x N64 x K128 ----
        uint32_t vbase = sm + V_OFF + (uint32_t)((kt & 1) * 16384);
        #pragma unroll
        for (int ks = 0; ks < 8; ks++) {
            uint32_t kbyte = (uint32_t)(ks * 32) + a_kb;
            uint32_t af[4], bv[4];
            ldsm4(af, sm + pbase + (kbyte >> 7) * 4096u
                      + sw128(a_row * 128 + (kbyte & 127)));
            ldsm4t(bv, vbase + sw128((uint32_t)((ks * 16 + (lane & 15)) * 128)
                                     + (uint32_t)(warp_n * 32) + (uint32_t)((lane >> 4) * 16)));
            mma16816h(ctx[0], af, bv);
            mma16816h(ctx[1], af, bv + 2);
        }
        __syncthreads();   // V buf[kt&1] consumed
        if (kt + 2 < 8) { load_v(kt + 2, kt & 1); CP_COMMIT(); }
    }

    // ---- normalized context write: [B,S,D] ----
    int b = bh >> 4, h = bh & 15;
    #pragma unroll
    for (int half = 0; half < 2; half++) {
        int r = warp_m * 16 + (lane >> 2) + half * 8;
        float inv = 1.0f / rowsumS[r];
        size_t o = ((size_t)(b * NS + q0 + r)) * ND + h * NDH;
        #pragma unroll
        for (int nt = 0; nt < 2; nt++) {
            int d = warp_n * 16 + nt * 8 + (lane & 3) * 2;
            float c0 = ctx[nt][half * 2 + 0] * inv;
            float c1 = ctx[nt][half * 2 + 1] * inv;
            *(float2*)&out_ctx[o + d] = make_float2(c0, c1);
        }
    }

    // ---- deferred att write: read P from smem, normalize, streaming store ----
    {
        int r = t >> 3;               // 0..31
        int c8 = t & 7;               // 16 cols each
        float inv = 1.0f / rowsumS[r];
        int col0 = c8 * 16;
        uint32_t half = (uint32_t)((col0 >> 6) * 4096);
        uint32_t boff = (uint32_t)(r * 128 + (col0 & 63) * 2);
        float* orow = out_att + ((size_t)bh * NS + q0 + r) * NS + col0;
        #pragma unroll 2
        for (int kt = 0; kt < 8; kt++) {
            char* tb = smraw + P_OFF + kt * 8192;
            uint4 d0 = *(uint4*)(tb + half + sw128(boff));
            uint4 d1 = *(uint4*)(tb + half + sw128(boff + 16));
            float* op = orow + kt * 128;
            const uint32_t* w0 = (const uint32_t*)&d0;
            const uint32_t* w1 = (const uint32_t*)&d1;
            {
                float2 a0 = __half22float2(*(__half2*)&w0[0]);
                float2 a1 = __half22float2(*(__half2*)&w0[1]);
                float2 a2 = __half22float2(*(__half2*)&w0[2]);
                float2 a3 = __half22float2(*(__half2*)&w0[3]);
                stcs4(op,     make_float4(a0.x * inv, a0.y * inv, a1.x * inv, a1.y * inv));
                stcs4(op + 4, make_float4(a2.x * inv, a2.y * inv, a3.x * inv, a3.y * inv));
            }
            {
                float2 a0 = __half22float2(*(__half2*)&w1[0]);
                float2 a1 = __half22float2(*(__half2*)&w1[1]);
                float2 a2 = __half22float2(*(__half2*)&w1[2]);
                float2 a3 = __half22float2(*(__half2*)&w1[3]);
                stcs4(op + 8,  make_float4(a0.x * inv, a0.y * inv, a1.x * inv, a1.y * inv));
                stcs4(op + 12, make_float4(a2.x * inv, a2.y * inv, a3.x * inv, a3.y * inv));
            }
        }
    }
}

extern "C" void kernel_launch(void* const* d_in, const int* in_sizes, int n_in,
                              void* d_out, int out_size) {
    const float* x  = (const float*)d_in[0];
    const float* Wq = (const float*)d_in[1];
    const float* bq = (const float*)d_in[2];
    const float* Wk = (const float*)d_in[3];
    const float* bk = (const float*)d_in[4];
    const float* Wv = (const float*)d_in[5];
    const float* bv = (const float*)d_in[6];
    // d_in[7] structure_bias: constant along the softmax axis -> cancels exactly.

    float* out_ctx = (float*)d_out;
    float* out_att = out_ctx + (size_t)NB * NS * ND;

    cudaFuncSetAttribute(qkv_mma_kernel, cudaFuncAttributeMaxDynamicSharedMemorySize, QKV_SMEM);
    cudaFuncSetAttribute(attn_mma_kernel, cudaFuncAttributeMaxDynamicSharedMemorySize, ATT_SMEM);

    prep_kernel<<<8192 + 3072, 256>>>(x, Wq, Wk, Wv);
    qkv_mma_kernel<<<dim3(24, 64), 256, QKV_SMEM>>>(bq, bk, bv);
    attn_mma_kernel<<<dim3(32, 128), 256, ATT_SMEM>>>(out_ctx, out_att);
}